// round 2
// baseline (speedup 1.0000x reference)
#include <cuda_runtime.h>
#include <math.h>

#define BB   8
#define CCH  64
#define HH   192
#define WWD  192
#define HWW  (HH*WWD)
#define NCLS 2
#define NSP  8

// ---------------- scratch (device globals; no allocation) ----------------
__device__ float g_space[BB*NCLS*NSP*HWW];   // [b][c][s][hw]
__device__ float g_A[BB*NCLS*HWW];           // [b][c][hw]
__device__ float g_R[BB*16*9*64];            // [b][sc][delta][e]
__device__ float g_S[BB*NCLS*NSP];           // per-map sums
__device__ float g_tok2[BB*NCLS*CCH];        // [b][c][d]
__device__ float g_U[BB*NCLS*CCH*9];         // [b][c][o][delta]
__device__ float g_y[BB*CCH*HWW];            // conv output pre-BN
__device__ float g_bnsum[CCH];
__device__ float g_bnsumsq[CCH];
__device__ float g_bnscale[CCH];
__device__ float g_bnbias[CCH];

__device__ __forceinline__ float sigmoidf_(float x){ return 1.f/(1.f+__expf(-x)); }

// ---------------- kernel 0: zero accumulators ----------------
__global__ void init_kernel(){
    int i = blockIdx.x*256 + threadIdx.x;
    if (i < BB*16*9*64) g_R[i] = 0.f;
    if (i < BB*NCLS*NSP) g_S[i] = 0.f;
    if (i < CCH){ g_bnsum[i] = 0.f; g_bnsumsq[i] = 0.f; }
}

// ---------------- kernel 1: space maps + per-map sums ----------------
// space[bc][0] = sigmoid(class_score); space[bc][1..7] = sigmoid(conv3x3(cp, W_cspace))
__global__ void space_kernel(const float* __restrict__ cs, const float* __restrict__ Wc){
    int h  = blockIdx.x;      // 0..191
    int bc = blockIdx.y;      // 0..15
    __shared__ float cp3[3*194];
    __shared__ float ssum[NSP];
    int t = threadIdx.x;      // 192
    if (t < NSP) ssum[t] = 0.f;
    const float* csp = cs + (size_t)bc*HWW;
    for (int idx = t; idx < 3*194; idx += 192){
        int r  = idx / 194;
        int wi = idx - r*194;
        int hh = h - 1 + r, ww = wi - 1;
        float v = 0.f;
        if (hh >= 0 && hh < HH && ww >= 0 && ww < WWD) v = sigmoidf_(csp[hh*WWD + ww]);
        cp3[idx] = v;
    }
    __syncthreads();
    int w = t;
    float sv[8];
    sv[0] = cp3[194 + w + 1];
    #pragma unroll
    for (int os = 0; os < 7; os++){
        float acc = 0.f;
        #pragma unroll
        for (int r = 0; r < 3; r++)
            #pragma unroll
            for (int c = 0; c < 3; c++)
                acc += Wc[os*9 + r*3 + c] * cp3[r*194 + w + c];
        sv[os+1] = sigmoidf_(acc);
    }
    float* sp = g_space + ((size_t)bc*NSP)*HWW + h*WWD + w;
    #pragma unroll
    for (int s = 0; s < 8; s++){
        sp[(size_t)s*HWW] = sv[s];
        float v = sv[s];
        #pragma unroll
        for (int off = 16; off > 0; off >>= 1) v += __shfl_down_sync(0xffffffffu, v, off);
        if ((t & 31) == 0) atomicAdd(&ssum[s], v);
    }
    __syncthreads();
    if (t < NSP) atomicAdd(&g_S[bc*NSP + t], ssum[t]);
}

// ---------------- kernel 2: correlation GEMM ----------------
// R[b][sc][delta=(ky,kx)][e] = sum_hw x[b,e,h+ky-1,w+kx-1] * space[b,sc,h,w]
// computed as: per image pixel p, B = x[e,p]; A = space[sc, p - dy, p - dx] (space zero-padded)
#define CH_ROWS 4
#define XS_STRIDE 68
__global__ void corr_kernel(const float* __restrict__ x){
    extern __shared__ float sm[];
    float* ss = sm;             // 16 * 582  (space: 16 maps x 3 rows x 194 cols)
    float* xs = sm + 16*582;    // 192 * 68  (x transposed: [w][e], padded)
    int b  = blockIdx.y;
    int h0 = blockIdx.x * CH_ROWS;
    int t  = threadIdx.x;       // 256
    int i  = t & 15;            // sc
    int j  = t >> 4;            // e-quad (4 channels)
    float acc[9][4];
    #pragma unroll
    for (int a = 0; a < 9; a++){ acc[a][0]=0.f; acc[a][1]=0.f; acc[a][2]=0.f; acc[a][3]=0.f; }

    for (int rr = 0; rr < CH_ROWS; rr++){
        int h = h0 + rr;
        // stage space rows h-1..h+1 for all 16 maps, zero-padded
        for (int idx = t; idx < 16*582; idx += 256){
            int sc  = idx / 582;
            int rem = idx - sc*582;
            int r   = rem / 194;
            int wi  = rem - r*194;
            int hh = h - 1 + r, ww = wi - 1;
            float v = 0.f;
            if (hh >= 0 && hh < HH && ww >= 0 && ww < WWD)
                v = g_space[((size_t)(b*16 + sc))*HWW + hh*WWD + ww];
            ss[idx] = v;
        }
        // stage x row h, transposed [w][e]
        for (int idx = t; idx < 64*192; idx += 256){
            int e = idx / 192;
            int w = idx - e*192;
            xs[w*XS_STRIDE + e] = x[((size_t)(b*64 + e))*HWW + h*WWD + w];
        }
        __syncthreads();

        const float* ssi = ss + i*582;
        float win[3][3];
        #pragma unroll
        for (int r = 0; r < 3; r++){
            win[r][0] = ssi[r*194 + 0];
            win[r][1] = ssi[r*194 + 1];
        }
        for (int k = 0; k < 192; k++){
            #pragma unroll
            for (int r = 0; r < 3; r++) win[r][2] = ssi[r*194 + k + 2];
            float4 xv = *(const float4*)&xs[k*XS_STRIDE + 4*j];
            #pragma unroll
            for (int r = 0; r < 3; r++){
                #pragma unroll
                for (int c = 0; c < 3; c++){
                    float f = win[r][c];
                    acc[r*3+c][0] += f*xv.x;
                    acc[r*3+c][1] += f*xv.y;
                    acc[r*3+c][2] += f*xv.z;
                    acc[r*3+c][3] += f*xv.w;
                }
            }
            #pragma unroll
            for (int r = 0; r < 3; r++){ win[r][0] = win[r][1]; win[r][1] = win[r][2]; }
        }
        __syncthreads();
    }
    // window index (r,c) -> delta index di = 8 - (r*3+c)
    #pragma unroll
    for (int r = 0; r < 3; r++){
        #pragma unroll
        for (int c = 0; c < 3; c++){
            int di = 8 - (r*3 + c);
            float* dst = &g_R[(((size_t)(b*16 + i))*9 + di)*64 + 4*j];
            atomicAdd(dst+0, acc[r*3+c][0]);
            atomicAdd(dst+1, acc[r*3+c][1]);
            atomicAdd(dst+2, acc[r*3+c][2]);
            atomicAdd(dst+3, acc[r*3+c][3]);
        }
    }
}

// ---------------- kernel 3: tok2[b,c,d] ----------------
// tok2 = sum_s (Wcs[s]/S[b,c,s]) * sum_{e,di} Wx[(s*64+d)*576 + e*9+di] * R[b, c*8+s, di, e]
__global__ void tok2_kernel(const float* __restrict__ Wx, const float* __restrict__ Wcs){
    int bc = blockIdx.x;            // 0..15
    int t  = threadIdx.x;           // 512 : s = t>>6, d = t&63
    __shared__ float Rs[4608];
    __shared__ float red[512];
    int b = bc >> 1, c = bc & 1;
    size_t base = ((size_t)(b*16 + c*8))*9*64;
    for (int idx = t; idx < 4608; idx += 512) Rs[idx] = g_R[base + idx];
    __syncthreads();
    int s = t >> 6, d = t & 63;
    float ws = Wcs[s] / g_S[bc*8 + s];
    const float* wx = Wx + ((size_t)(s*64 + d))*576;
    const float* rr = Rs + s*576;
    float p = 0.f;
    for (int e = 0; e < 64; e++){
        #pragma unroll
        for (int di = 0; di < 9; di++)
            p += wx[e*9 + di] * rr[di*64 + e];
    }
    red[t] = ws * p;
    __syncthreads();
    if (t < 64){
        float acc = 0.f;
        #pragma unroll
        for (int ss2 = 0; ss2 < 8; ss2++) acc += red[ss2*64 + t];
        g_tok2[bc*64 + t] = acc;
    }
}

// ---------------- kernel 4: attention maps A ----------------
__global__ void attn_kernel(const float* __restrict__ cs, const float* __restrict__ Wcv,
                            const float* __restrict__ Wattn, const float* __restrict__ Wcomb){
    int bc = blockIdx.y;
    int hw = blockIdx.x*256 + threadIdx.x;
    float cp = sigmoidf_(cs[(size_t)bc*HWW + hw]);
    float a = 0.f;
    #pragma unroll
    for (int s = 0; s < 8; s++) a += Wcomb[s]*Wcv[s]*sigmoidf_(cp*Wattn[s]);
    g_A[(size_t)bc*HWW + hw] = a;
}

// ---------------- kernel 5: U[b,c,o,di] = sum_d Wsingle[o,d,di]*tok2[b,c,d] ----------------
__global__ void u_kernel(const float* __restrict__ Wsingle){
    int bc = blockIdx.x;
    int t  = threadIdx.x;           // 576
    __shared__ float tk[64];
    if (t < 64) tk[t] = g_tok2[bc*64 + t];
    __syncthreads();
    int o = t / 9, di = t - o*9;
    float acc = 0.f;
    for (int d = 0; d < 64; d++) acc += Wsingle[((size_t)(o*64 + d))*9 + di] * tk[d];
    g_U[(size_t)bc*576 + t] = acc;
}

// ---------------- kernel 6: y = "conv" of A with per-batch U + BN partial sums ----------------
#define YROWS 4
#define AT_RS 196
__global__ void y_kernel(){
    __shared__ float At[2*6*AT_RS];
    __shared__ float Us[1152];
    __shared__ float bs[64], bsq[64];
    int b  = blockIdx.y;
    int h0 = blockIdx.x * YROWS;
    int t  = threadIdx.x;           // 192
    if (t < 64){ bs[t] = 0.f; bsq[t] = 0.f; }
    for (int idx = t; idx < 2*6*194; idx += 192){
        int ccv = idx / (6*194);
        int rem = idx - ccv*(6*194);
        int r   = rem / 194;
        int wi  = rem - r*194;
        int hh = h0 - 1 + r, ww = wi - 1;
        float v = 0.f;
        if (hh >= 0 && hh < HH && ww >= 0 && ww < WWD)
            v = g_A[((size_t)(b*2 + ccv))*HWW + hh*WWD + ww];
        At[ccv*(6*AT_RS) + r*AT_RS + wi] = v;
    }
    for (int idx = t; idx < 1152; idx += 192) Us[idx] = g_U[(size_t)b*1152 + idx];
    __syncthreads();

    int rr = t / 48, wq = t - rr*48;
    int w0 = wq * 4;
    float* yrow = g_y + ((size_t)(b*64))*HWW + (h0 + rr)*WWD + w0;
    for (int o = 0; o < 64; o++){
        float u[2][9];
        #pragma unroll
        for (int ccv = 0; ccv < 2; ccv++)
            #pragma unroll
            for (int di = 0; di < 9; di++) u[ccv][di] = Us[(ccv*64 + o)*9 + di];
        float o0=0.f, o1=0.f, o2=0.f, o3=0.f;
        #pragma unroll
        for (int ccv = 0; ccv < 2; ccv++){
            const float* Ab = At + ccv*(6*AT_RS);
            #pragma unroll
            for (int ky = 0; ky < 3; ky++){
                const float* arow = Ab + (rr + ky)*AT_RS + w0;
                float a0=arow[0], a1=arow[1], a2=arow[2], a3=arow[3], a4=arow[4], a5=arow[5];
                float u0=u[ccv][ky*3+0], u1=u[ccv][ky*3+1], u2=u[ccv][ky*3+2];
                o0 += u0*a0 + u1*a1 + u2*a2;
                o1 += u0*a1 + u1*a2 + u2*a3;
                o2 += u0*a2 + u1*a3 + u2*a4;
                o3 += u0*a3 + u1*a4 + u2*a5;
            }
        }
        *(float4*)&yrow[(size_t)o*HWW] = make_float4(o0, o1, o2, o3);
        float s1 = o0+o1+o2+o3;
        float s2 = o0*o0+o1*o1+o2*o2+o3*o3;
        #pragma unroll
        for (int off = 16; off > 0; off >>= 1){
            s1 += __shfl_down_sync(0xffffffffu, s1, off);
            s2 += __shfl_down_sync(0xffffffffu, s2, off);
        }
        if ((t & 31) == 0){ atomicAdd(&bs[o], s1); atomicAdd(&bsq[o], s2); }
    }
    __syncthreads();
    if (t < 64){ atomicAdd(&g_bnsum[t], bs[t]); atomicAdd(&g_bnsumsq[t], bsq[t]); }
}

// ---------------- kernel 7: BN finalize ----------------
__global__ void bnfin_kernel(const float* __restrict__ gamma, const float* __restrict__ beta){
    int o = threadIdx.x;
    float n = (float)(BB*HWW);
    float mean = g_bnsum[o] / n;
    float var  = g_bnsumsq[o] / n - mean*mean;
    float sc = gamma[o] * rsqrtf(var + 1e-5f);
    g_bnscale[o] = sc;
    g_bnbias[o]  = beta[o] - mean*sc;
}

// ---------------- kernel 8: out = x + relu(y*scale + bias) ----------------
__global__ void out_kernel(const float* __restrict__ x, float* __restrict__ out){
    int idx = blockIdx.x*256 + threadIdx.x;   // float4 index
    size_t i = (size_t)idx * 4;
    int o = (int)((i / HWW) & 63);
    float sc = g_bnscale[o], bi = g_bnbias[o];
    float4 xv = *(const float4*)&x[i];
    float4 yv = *(const float4*)&g_y[i];
    float4 r;
    r.x = xv.x + fmaxf(yv.x*sc + bi, 0.f);
    r.y = xv.y + fmaxf(yv.y*sc + bi, 0.f);
    r.z = xv.z + fmaxf(yv.z*sc + bi, 0.f);
    r.w = xv.w + fmaxf(yv.w*sc + bi, 0.f);
    *(float4*)&out[i] = r;
}

// ---------------- launcher ----------------
extern "C" void kernel_launch(void* const* d_in, const int* in_sizes, int n_in,
                              void* d_out, int out_size){
    const float* x      = (const float*)d_in[0];
    const float* cs     = (const float*)d_in[1];
    const float* Wc     = (const float*)d_in[2];   // (7,1,3,3)
    const float* Wx     = (const float*)d_in[3];   // (512,64,3,3)
    const float* Wcs    = (const float*)d_in[4];   // (8,)
    const float* Wcv    = (const float*)d_in[5];   // (8,)
    const float* Wattn  = (const float*)d_in[6];   // (8,)
    const float* Wcomb  = (const float*)d_in[7];   // (8,)
    const float* Wsing  = (const float*)d_in[8];   // (64,64,3,3)
    const float* gamma  = (const float*)d_in[9];
    const float* beta   = (const float*)d_in[10];
    float* out = (float*)d_out;

    init_kernel<<<290, 256>>>();
    space_kernel<<<dim3(HH, BB*NCLS), 192>>>(cs, Wc);

    int corr_smem = (16*582 + 192*XS_STRIDE) * 4;   // 89472 bytes
    cudaFuncSetAttribute(corr_kernel, cudaFuncAttributeMaxDynamicSharedMemorySize, corr_smem);
    corr_kernel<<<dim3(HH/CH_ROWS, BB), 256, corr_smem>>>(x);

    tok2_kernel<<<16, 512>>>(Wx, Wcs);
    attn_kernel<<<dim3(HWW/256, BB*NCLS), 256>>>(cs, Wcv, Wattn, Wcomb);
    u_kernel<<<16, 576>>>(Wsing);
    y_kernel<<<dim3(HH/YROWS, BB), 192>>>();
    bnfin_kernel<<<1, 64>>>(gamma, beta);
    out_kernel<<<(BB*CCH*HWW/4)/256, 256>>>(x, out);
}

// round 4
// speedup vs baseline: 1.2816x; 1.2816x over previous
#include <cuda_runtime.h>
#include <math.h>

#define BB   8
#define CCH  64
#define HH   192
#define WWD  192
#define HWW  (HH*WWD)
#define NCLS 2
#define NSP  8

// ---------------- scratch (device globals; no allocation) ----------------
__device__ float g_space[BB*NCLS*NSP*HWW];   // [b][c][s][hw]
__device__ float g_A[BB*NCLS*HWW];           // [b][c][hw]
__device__ float g_R[BB*16*9*64];            // [b][sc][delta][e]
__device__ float g_S[BB*NCLS*NSP];           // per-map sums
__device__ float g_tok2[BB*NCLS*CCH];        // [b][c][d]
__device__ float g_U[BB*NCLS*CCH*9];         // [b][c][o][delta]
__device__ float g_bnsum[CCH];
__device__ float g_bnsumsq[CCH];
__device__ float g_bnscale[CCH];
__device__ float g_bnbias[CCH];

__device__ __forceinline__ float sigmoidf_(float x){ return 1.f/(1.f+__expf(-x)); }

// ---------------- kernel 0: zero accumulators ----------------
__global__ void init_kernel(){
    int i = blockIdx.x*256 + threadIdx.x;
    if (i < BB*16*9*64) g_R[i] = 0.f;
    if (i < BB*NCLS*NSP) g_S[i] = 0.f;
    if (i < BB*NCLS*CCH) g_tok2[i] = 0.f;
    if (i < CCH){ g_bnsum[i] = 0.f; g_bnsumsq[i] = 0.f; }
}

// ---------------- kernel 1: space maps + per-map sums ----------------
__global__ void space_kernel(const float* __restrict__ cs, const float* __restrict__ Wc){
    int h  = blockIdx.x;      // 0..191
    int bc = blockIdx.y;      // 0..15
    __shared__ float cp3[3*194];
    __shared__ float ssum[NSP];
    int t = threadIdx.x;      // 192
    if (t < NSP) ssum[t] = 0.f;
    const float* csp = cs + (size_t)bc*HWW;
    for (int idx = t; idx < 3*194; idx += 192){
        int r  = idx / 194;
        int wi = idx - r*194;
        int hh = h - 1 + r, ww = wi - 1;
        float v = 0.f;
        if (hh >= 0 && hh < HH && ww >= 0 && ww < WWD) v = sigmoidf_(csp[hh*WWD + ww]);
        cp3[idx] = v;
    }
    __syncthreads();
    int w = t;
    float sv[8];
    sv[0] = cp3[194 + w + 1];
    #pragma unroll
    for (int os = 0; os < 7; os++){
        float acc = 0.f;
        #pragma unroll
        for (int r = 0; r < 3; r++)
            #pragma unroll
            for (int c = 0; c < 3; c++)
                acc += Wc[os*9 + r*3 + c] * cp3[r*194 + w + c];
        sv[os+1] = sigmoidf_(acc);
    }
    float* sp = g_space + ((size_t)bc*NSP)*HWW + h*WWD + w;
    #pragma unroll
    for (int s = 0; s < 8; s++){
        sp[(size_t)s*HWW] = sv[s];
        float v = sv[s];
        #pragma unroll
        for (int off = 16; off > 0; off >>= 1) v += __shfl_down_sync(0xffffffffu, v, off);
        if ((t & 31) == 0) atomicAdd(&ssum[s], v);
    }
    __syncthreads();
    if (t < NSP) atomicAdd(&g_S[bc*NSP + t], ssum[t]);
}

// ---------------- kernel 2: correlation GEMM ----------------
#define CH_ROWS 4
#define XS_STRIDE 68
__global__ void corr_kernel(const float* __restrict__ x){
    extern __shared__ float sm[];
    float* ss = sm;             // 16 * 582
    float* xs = sm + 16*582;    // 192 * 68
    int b  = blockIdx.y;
    int h0 = blockIdx.x * CH_ROWS;
    int t  = threadIdx.x;       // 256
    int i  = t & 15;            // sc
    int j  = t >> 4;            // e-quad
    float acc[9][4];
    #pragma unroll
    for (int a = 0; a < 9; a++){ acc[a][0]=0.f; acc[a][1]=0.f; acc[a][2]=0.f; acc[a][3]=0.f; }

    for (int rr = 0; rr < CH_ROWS; rr++){
        int h = h0 + rr;
        for (int idx = t; idx < 16*582; idx += 256){
            int sc  = idx / 582;
            int rem = idx - sc*582;
            int r   = rem / 194;
            int wi  = rem - r*194;
            int hh = h - 1 + r, ww = wi - 1;
            float v = 0.f;
            if (hh >= 0 && hh < HH && ww >= 0 && ww < WWD)
                v = g_space[((size_t)(b*16 + sc))*HWW + hh*WWD + ww];
            ss[idx] = v;
        }
        for (int idx = t; idx < 64*192; idx += 256){
            int e = idx / 192;
            int w = idx - e*192;
            xs[w*XS_STRIDE + e] = x[((size_t)(b*64 + e))*HWW + h*WWD + w];
        }
        __syncthreads();

        const float* ssi = ss + i*582;
        float win[3][3];
        #pragma unroll
        for (int r = 0; r < 3; r++){
            win[r][0] = ssi[r*194 + 0];
            win[r][1] = ssi[r*194 + 1];
        }
        for (int k = 0; k < 192; k++){
            #pragma unroll
            for (int r = 0; r < 3; r++) win[r][2] = ssi[r*194 + k + 2];
            float4 xv = *(const float4*)&xs[k*XS_STRIDE + 4*j];
            #pragma unroll
            for (int r = 0; r < 3; r++){
                #pragma unroll
                for (int c = 0; c < 3; c++){
                    float f = win[r][c];
                    acc[r*3+c][0] += f*xv.x;
                    acc[r*3+c][1] += f*xv.y;
                    acc[r*3+c][2] += f*xv.z;
                    acc[r*3+c][3] += f*xv.w;
                }
            }
            #pragma unroll
            for (int r = 0; r < 3; r++){ win[r][0] = win[r][1]; win[r][1] = win[r][2]; }
        }
        __syncthreads();
    }
    #pragma unroll
    for (int r = 0; r < 3; r++){
        #pragma unroll
        for (int c = 0; c < 3; c++){
            int di = 8 - (r*3 + c);
            float* dst = &g_R[(((size_t)(b*16 + i))*9 + di)*64 + 4*j];
            atomicAdd(dst+0, acc[r*3+c][0]);
            atomicAdd(dst+1, acc[r*3+c][1]);
            atomicAdd(dst+2, acc[r*3+c][2]);
            atomicAdd(dst+3, acc[r*3+c][3]);
        }
    }
}

// ---------------- kernel 3: tok2 (rewritten: 512 blocks, smem-staged) ----------------
// block = (s*64+d); tok2[bc,d] += ws(bc,s) * dot(Wx_row(s,d), R[bc,s,:])
__global__ void tok2_kernel(const float* __restrict__ Wx, const float* __restrict__ Wcs){
    __shared__ float wxs[576];          // reordered to [di*64+e]
    __shared__ float Rs[16*576];        // [bc][di*64+e]
    int s = blockIdx.x >> 6;
    int d = blockIdx.x & 63;
    int t = threadIdx.x;                // 256
    const float* wx = Wx + ((size_t)(s*64 + d))*576;
    for (int idx = t; idx < 576; idx += 256){
        int di = idx >> 6, e = idx & 63;
        wxs[idx] = wx[e*9 + di];
    }
    for (int idx = t; idx < 16*576; idx += 256){
        int bc = idx / 576, k = idx - bc*576;
        int b = bc >> 1, c = bc & 1;
        Rs[idx] = g_R[((size_t)(b*16 + c*8 + s))*576 + k];
    }
    __syncthreads();
    int bc = t >> 4, q = t & 15;
    const float* rr = Rs + bc*576;
    float p = 0.f;
    #pragma unroll 9
    for (int j = 0; j < 36; j++){
        int k = q*36 + j;
        p += wxs[k]*rr[k];
    }
    #pragma unroll
    for (int off = 8; off > 0; off >>= 1) p += __shfl_down_sync(0xffffffffu, p, off, 16);
    if (q == 0){
        float ws = Wcs[s] / g_S[bc*8 + s];
        atomicAdd(&g_tok2[bc*64 + d], ws*p);
    }
}

// ---------------- kernel 4: attention maps A ----------------
__global__ void attn_kernel(const float* __restrict__ cs, const float* __restrict__ Wcv,
                            const float* __restrict__ Wattn, const float* __restrict__ Wcomb){
    int bc = blockIdx.y;
    int hw = blockIdx.x*256 + threadIdx.x;
    float cp = sigmoidf_(cs[(size_t)bc*HWW + hw]);
    float a = 0.f;
    #pragma unroll
    for (int s = 0; s < 8; s++) a += Wcomb[s]*Wcv[s]*sigmoidf_(cp*Wattn[s]);
    g_A[(size_t)bc*HWW + hw] = a;
}

// ---------------- kernel 5: U[b,c,o,di] ----------------
__global__ void u_kernel(const float* __restrict__ Wsingle){
    int bc = blockIdx.x;
    int t  = threadIdx.x;           // 576
    __shared__ float tk[64];
    if (t < 64) tk[t] = g_tok2[bc*64 + t];
    __syncthreads();
    int o = t / 9, di = t - o*9;
    float acc = 0.f;
    for (int d = 0; d < 64; d++) acc += Wsingle[((size_t)(o*64 + d))*9 + di] * tk[d];
    g_U[(size_t)bc*576 + t] = acc;
}

// ---------------- shared y-compute helper (stage + per-o 4-pixel conv) ----------------
#define YROWS 4
#define AT_RS 196
__device__ __forceinline__ void stage_AU(float* At, float* Us, int b, int h0, int t){
    for (int idx = t; idx < 2*6*194; idx += 192){
        int ccv = idx / (6*194);
        int rem = idx - ccv*(6*194);
        int r   = rem / 194;
        int wi  = rem - r*194;
        int hh = h0 - 1 + r, ww = wi - 1;
        float v = 0.f;
        if (hh >= 0 && hh < HH && ww >= 0 && ww < WWD)
            v = g_A[((size_t)(b*2 + ccv))*HWW + hh*WWD + ww];
        At[ccv*(6*AT_RS) + r*AT_RS + wi] = v;
    }
    for (int idx = t; idx < 1152; idx += 192) Us[idx] = g_U[(size_t)b*1152 + idx];
}

__device__ __forceinline__ void y_quad(const float* At, const float* Us, int rr, int w0, int o,
                                       float& o0, float& o1, float& o2, float& o3){
    o0=0.f; o1=0.f; o2=0.f; o3=0.f;
    #pragma unroll
    for (int ccv = 0; ccv < 2; ccv++){
        const float* Ab = At + ccv*(6*AT_RS);
        const float* u  = Us + (ccv*64 + o)*9;
        #pragma unroll
        for (int ky = 0; ky < 3; ky++){
            const float* arow = Ab + (rr + ky)*AT_RS + w0;
            float a0=arow[0], a1=arow[1], a2=arow[2], a3=arow[3], a4=arow[4], a5=arow[5];
            float u0=u[ky*3+0], u1=u[ky*3+1], u2=u[ky*3+2];
            o0 += u0*a0 + u1*a1 + u2*a2;
            o1 += u0*a1 + u1*a2 + u2*a3;
            o2 += u0*a2 + u1*a3 + u2*a4;
            o3 += u0*a3 + u1*a4 + u2*a5;
        }
    }
}

// ---------------- kernel 6: BN stats only (no y store) ----------------
__global__ void y_kernel(){
    __shared__ float At[2*6*AT_RS];
    __shared__ float Us[1152];
    __shared__ float bs[64], bsq[64];
    int b  = blockIdx.y;
    int h0 = blockIdx.x * YROWS;
    int t  = threadIdx.x;           // 192
    if (t < 64){ bs[t] = 0.f; bsq[t] = 0.f; }
    stage_AU(At, Us, b, h0, t);
    __syncthreads();

    int rr = t / 48, wq = t - rr*48;
    int w0 = wq * 4;
    for (int o = 0; o < 64; o++){
        float o0,o1,o2,o3;
        y_quad(At, Us, rr, w0, o, o0, o1, o2, o3);
        float s1 = o0+o1+o2+o3;
        float s2 = o0*o0+o1*o1+o2*o2+o3*o3;
        #pragma unroll
        for (int off = 16; off > 0; off >>= 1){
            s1 += __shfl_down_sync(0xffffffffu, s1, off);
            s2 += __shfl_down_sync(0xffffffffu, s2, off);
        }
        if ((t & 31) == 0){ atomicAdd(&bs[o], s1); atomicAdd(&bsq[o], s2); }
    }
    __syncthreads();
    if (t < 64){ atomicAdd(&g_bnsum[t], bs[t]); atomicAdd(&g_bnsumsq[t], bsq[t]); }
}

// ---------------- kernel 7: BN finalize ----------------
__global__ void bnfin_kernel(const float* __restrict__ gamma, const float* __restrict__ beta){
    int o = threadIdx.x;
    float n = (float)(BB*HWW);
    float mean = g_bnsum[o] / n;
    float var  = g_bnsumsq[o] / n - mean*mean;
    float sc = gamma[o] * rsqrtf(var + 1e-5f);
    g_bnscale[o] = sc;
    g_bnbias[o]  = beta[o] - mean*sc;
}

// ---------------- kernel 8: recompute y, apply BN+ReLU, add x ----------------
__global__ void out_kernel(const float* __restrict__ x, float* __restrict__ out){
    __shared__ float At[2*6*AT_RS];
    __shared__ float Us[1152];
    __shared__ float scs[64], bis[64];
    int b  = blockIdx.y;
    int h0 = blockIdx.x * YROWS;
    int t  = threadIdx.x;           // 192
    if (t < 64){ scs[t] = g_bnscale[t]; bis[t] = g_bnbias[t]; }
    stage_AU(At, Us, b, h0, t);
    __syncthreads();

    int rr = t / 48, wq = t - rr*48;
    int w0 = wq * 4;
    size_t rowoff = ((size_t)(b*64))*HWW + (size_t)(h0 + rr)*WWD + w0;
    for (int o = 0; o < 64; o++){
        float o0,o1,o2,o3;
        y_quad(At, Us, rr, w0, o, o0, o1, o2, o3);
        float sc = scs[o], bi = bis[o];
        float4 xv = *(const float4*)&x[rowoff + (size_t)o*HWW];
        float4 r;
        r.x = xv.x + fmaxf(o0*sc + bi, 0.f);
        r.y = xv.y + fmaxf(o1*sc + bi, 0.f);
        r.z = xv.z + fmaxf(o2*sc + bi, 0.f);
        r.w = xv.w + fmaxf(o3*sc + bi, 0.f);
        *(float4*)&out[rowoff + (size_t)o*HWW] = r;
    }
}

// ---------------- launcher ----------------
extern "C" void kernel_launch(void* const* d_in, const int* in_sizes, int n_in,
                              void* d_out, int out_size){
    const float* x      = (const float*)d_in[0];
    const float* cs     = (const float*)d_in[1];
    const float* Wc     = (const float*)d_in[2];   // (7,1,3,3)
    const float* Wx     = (const float*)d_in[3];   // (512,64,3,3)
    const float* Wcs    = (const float*)d_in[4];   // (8,)
    const float* Wcv    = (const float*)d_in[5];   // (8,)
    const float* Wattn  = (const float*)d_in[6];   // (8,)
    const float* Wcomb  = (const float*)d_in[7];   // (8,)
    const float* Wsing  = (const float*)d_in[8];   // (64,64,3,3)
    const float* gamma  = (const float*)d_in[9];
    const float* beta   = (const float*)d_in[10];
    float* out = (float*)d_out;

    init_kernel<<<290, 256>>>();
    space_kernel<<<dim3(HH, BB*NCLS), 192>>>(cs, Wc);

    int corr_smem = (16*582 + 192*XS_STRIDE) * 4;   // 89472 bytes
    cudaFuncSetAttribute(corr_kernel, cudaFuncAttributeMaxDynamicSharedMemorySize, corr_smem);
    corr_kernel<<<dim3(HH/CH_ROWS, BB), 256, corr_smem>>>(x);

    tok2_kernel<<<512, 256>>>(Wx, Wcs);
    attn_kernel<<<dim3(HWW/256, BB*NCLS), 256>>>(cs, Wcv, Wattn, Wcomb);
    u_kernel<<<16, 576>>>(Wsing);
    y_kernel<<<dim3(HH/YROWS, BB), 192>>>();
    bnfin_kernel<<<1, 64>>>(gamma, beta);
    out_kernel<<<dim3(HH/YROWS, BB), 192>>>(x, out);
}

// round 5
// speedup vs baseline: 1.7287x; 1.3488x over previous
#include <cuda_runtime.h>
#include <math.h>

#define BB   8
#define CCH  64
#define HH   192
#define WWD  192
#define HWW  (HH*WWD)
#define NCLS 2
#define NSP  8

typedef unsigned long long u64;

// packed f32x2 helpers (Blackwell; FFMA2 only reachable via PTX)
#define FMA2(acc, a, b)   asm("fma.rn.f32x2 %0, %1, %2, %0;" : "+l"(acc) : "l"(a), "l"(b))
#define PACKD(d, f)       asm("mov.b64 %0, {%1, %1};" : "=l"(d) : "f"(f))
#define PACK2(d, lo, hi)  asm("mov.b64 %0, {%1, %2};" : "=l"(d) : "f"(lo), "f"(hi))
#define UNPK(lo, hi, d)   asm("mov.b64 {%0, %1}, %2;" : "=f"(lo), "=f"(hi) : "l"(d))

// ---------------- scratch (device globals; no allocation) ----------------
__device__ float g_space[BB*NCLS*NSP*HWW];   // [b][c][s][hw]
__device__ float g_A[BB*NCLS*HWW];           // [b][c][hw]
__device__ float g_R[BB*16*9*64];            // [b][sc][delta][e]
__device__ float g_S[BB*NCLS*NSP];           // per-map sums
__device__ float g_tok2[BB*NCLS*CCH];        // [b][c][d]
__device__ float g_U[BB*NCLS*CCH*9];         // [b][c][o][delta]
__device__ float g_bnsum[CCH];
__device__ float g_bnsumsq[CCH];
__device__ float g_bnscale[CCH];
__device__ float g_bnbias[CCH];

__device__ __forceinline__ float sigmoidf_(float x){ return 1.f/(1.f+__expf(-x)); }

// ---------------- kernel 0: zero accumulators ----------------
__global__ void init_kernel(){
    int i = blockIdx.x*256 + threadIdx.x;
    if (i < BB*16*9*64) g_R[i] = 0.f;
    if (i < BB*NCLS*NSP) g_S[i] = 0.f;
    if (i < BB*NCLS*CCH) g_tok2[i] = 0.f;
    if (i < CCH){ g_bnsum[i] = 0.f; g_bnsumsq[i] = 0.f; }
}

// ---------------- kernel 1: space maps + per-map sums ----------------
__global__ void space_kernel(const float* __restrict__ cs, const float* __restrict__ Wc){
    int h  = blockIdx.x;      // 0..191
    int bc = blockIdx.y;      // 0..15
    __shared__ float cp3[3*194];
    __shared__ float ssum[NSP];
    int t = threadIdx.x;      // 192
    if (t < NSP) ssum[t] = 0.f;
    const float* csp = cs + (size_t)bc*HWW;
    for (int idx = t; idx < 3*194; idx += 192){
        int r  = idx / 194;
        int wi = idx - r*194;
        int hh = h - 1 + r, ww = wi - 1;
        float v = 0.f;
        if (hh >= 0 && hh < HH && ww >= 0 && ww < WWD) v = sigmoidf_(csp[hh*WWD + ww]);
        cp3[idx] = v;
    }
    __syncthreads();
    int w = t;
    float sv[8];
    sv[0] = cp3[194 + w + 1];
    #pragma unroll
    for (int os = 0; os < 7; os++){
        float acc = 0.f;
        #pragma unroll
        for (int r = 0; r < 3; r++)
            #pragma unroll
            for (int c = 0; c < 3; c++)
                acc += Wc[os*9 + r*3 + c] * cp3[r*194 + w + c];
        sv[os+1] = sigmoidf_(acc);
    }
    float* sp = g_space + ((size_t)bc*NSP)*HWW + h*WWD + w;
    #pragma unroll
    for (int s = 0; s < 8; s++){
        sp[(size_t)s*HWW] = sv[s];
        float v = sv[s];
        #pragma unroll
        for (int off = 16; off > 0; off >>= 1) v += __shfl_down_sync(0xffffffffu, v, off);
        if ((t & 31) == 0) atomicAdd(&ssum[s], v);
    }
    __syncthreads();
    if (t < NSP) atomicAdd(&g_S[bc*NSP + t], ssum[t]);
}

// ---------------- kernel 2: correlation GEMM (f32x2 packed) ----------------
#define CH_ROWS 3
#define XS_STRIDE 66
__global__ void corr_kernel(const float* __restrict__ x){
    extern __shared__ float sm[];
    float* ss = sm;             // 16 * 582  (space: 16 maps x 3 rows x 194 cols)
    float* xs = sm + 16*582;    // 192 * 66  (x transposed: [w][e], padded)
    int b  = blockIdx.y;
    int h0 = blockIdx.x * CH_ROWS;
    int t  = threadIdx.x;       // 256
    int i  = t & 15;            // sc
    int j  = t >> 4;            // e-quad (4 channels)
    u64 acc[9][2];
    #pragma unroll
    for (int a = 0; a < 9; a++){ acc[a][0] = 0ull; acc[a][1] = 0ull; }

    for (int rr = 0; rr < CH_ROWS; rr++){
        int h = h0 + rr;
        for (int idx = t; idx < 16*582; idx += 256){
            int sc  = idx / 582;
            int rem = idx - sc*582;
            int r   = rem / 194;
            int wi  = rem - r*194;
            int hh = h - 1 + r, ww = wi - 1;
            float v = 0.f;
            if (hh >= 0 && hh < HH && ww >= 0 && ww < WWD)
                v = g_space[((size_t)(b*16 + sc))*HWW + hh*WWD + ww];
            ss[idx] = v;
        }
        for (int idx = t; idx < 64*192; idx += 256){
            int e = idx / 192;
            int w = idx - e*192;
            xs[w*XS_STRIDE + e] = x[((size_t)(b*64 + e))*HWW + h*WWD + w];
        }
        __syncthreads();

        const float* ssi = ss + i*582;
        u64 winp[3][3];
        #pragma unroll
        for (int r = 0; r < 3; r++){
            float f0 = ssi[r*194 + 0];
            float f1 = ssi[r*194 + 1];
            PACKD(winp[r][0], f0);
            PACKD(winp[r][1], f1);
        }
        #pragma unroll 3
        for (int k = 0; k < 192; k++){
            #pragma unroll
            for (int r = 0; r < 3; r++){
                float f = ssi[r*194 + k + 2];
                PACKD(winp[r][2], f);
            }
            const u64* xp = (const u64*)&xs[k*XS_STRIDE + 4*j];
            u64 x01 = xp[0], x23 = xp[1];
            #pragma unroll
            for (int r = 0; r < 3; r++){
                #pragma unroll
                for (int c = 0; c < 3; c++){
                    FMA2(acc[r*3+c][0], winp[r][c], x01);
                    FMA2(acc[r*3+c][1], winp[r][c], x23);
                }
            }
            #pragma unroll
            for (int r = 0; r < 3; r++){ winp[r][0] = winp[r][1]; winp[r][1] = winp[r][2]; }
        }
        __syncthreads();
    }
    // window index (r,c) -> delta index di = 8 - (r*3+c)
    #pragma unroll
    for (int r = 0; r < 3; r++){
        #pragma unroll
        for (int c = 0; c < 3; c++){
            int di = 8 - (r*3 + c);
            float* dst = &g_R[(((size_t)(b*16 + i))*9 + di)*64 + 4*j];
            float e0,e1,e2,e3;
            UNPK(e0, e1, acc[r*3+c][0]);
            UNPK(e2, e3, acc[r*3+c][1]);
            atomicAdd(dst+0, e0);
            atomicAdd(dst+1, e1);
            atomicAdd(dst+2, e2);
            atomicAdd(dst+3, e3);
        }
    }
}

// ---------------- kernel 3: tok2 ----------------
__global__ void tok2_kernel(const float* __restrict__ Wx, const float* __restrict__ Wcs){
    __shared__ float wxs[576];          // reordered to [di*64+e]
    __shared__ float Rs[16*576];        // [bc][di*64+e]
    int s = blockIdx.x >> 6;
    int d = blockIdx.x & 63;
    int t = threadIdx.x;                // 256
    const float* wx = Wx + ((size_t)(s*64 + d))*576;
    for (int idx = t; idx < 576; idx += 256){
        int di = idx >> 6, e = idx & 63;
        wxs[idx] = wx[e*9 + di];
    }
    for (int idx = t; idx < 16*576; idx += 256){
        int bc = idx / 576, k = idx - bc*576;
        int b = bc >> 1, c = bc & 1;
        Rs[idx] = g_R[((size_t)(b*16 + c*8 + s))*576 + k];
    }
    __syncthreads();
    int bc = t >> 4, q = t & 15;
    const float* rr = Rs + bc*576;
    float p = 0.f;
    #pragma unroll 9
    for (int jj = 0; jj < 36; jj++){
        int k = q*36 + jj;
        p += wxs[k]*rr[k];
    }
    #pragma unroll
    for (int off = 8; off > 0; off >>= 1) p += __shfl_down_sync(0xffffffffu, p, off, 16);
    if (q == 0){
        float ws = Wcs[s] / g_S[bc*8 + s];
        atomicAdd(&g_tok2[bc*64 + d], ws*p);
    }
}

// ---------------- kernel 4: attention maps A ----------------
__global__ void attn_kernel(const float* __restrict__ cs, const float* __restrict__ Wcv,
                            const float* __restrict__ Wattn, const float* __restrict__ Wcomb){
    int bc = blockIdx.y;
    int hw = blockIdx.x*256 + threadIdx.x;
    float cp = sigmoidf_(cs[(size_t)bc*HWW + hw]);
    float a = 0.f;
    #pragma unroll
    for (int s = 0; s < 8; s++) a += Wcomb[s]*Wcv[s]*sigmoidf_(cp*Wattn[s]);
    g_A[(size_t)bc*HWW + hw] = a;
}

// ---------------- kernel 5: U[b,c,o,di] ----------------
__global__ void u_kernel(const float* __restrict__ Wsingle){
    int bc = blockIdx.x;
    int t  = threadIdx.x;           // 576
    __shared__ float tk[64];
    if (t < 64) tk[t] = g_tok2[bc*64 + t];
    __syncthreads();
    int o = t / 9, di = t - o*9;
    float acc = 0.f;
    for (int d = 0; d < 64; d++) acc += Wsingle[((size_t)(o*64 + d))*9 + di] * tk[d];
    g_U[(size_t)bc*576 + t] = acc;
}

// ---------------- shared y-compute helpers ----------------
#define YROWS 4
#define AT_RS 196
// stage A rows (zero-padded) and U duplicated as (u,u) pairs
__device__ __forceinline__ void stage_AU2(float* At, float* Us2, int b, int h0, int t){
    for (int idx = t; idx < 2*6*194; idx += 192){
        int ccv = idx / (6*194);
        int rem = idx - ccv*(6*194);
        int r   = rem / 194;
        int wi  = rem - r*194;
        int hh = h0 - 1 + r, ww = wi - 1;
        float v = 0.f;
        if (hh >= 0 && hh < HH && ww >= 0 && ww < WWD)
            v = g_A[((size_t)(b*2 + ccv))*HWW + hh*WWD + ww];
        At[ccv*(6*AT_RS) + r*AT_RS + wi] = v;
    }
    for (int idx = t; idx < 1152; idx += 192){
        float v = g_U[(size_t)b*1152 + idx];
        Us2[2*idx]   = v;
        Us2[2*idx+1] = v;
    }
}

// hoist the A window for this thread into 30 packed pairs (independent of o)
__device__ __forceinline__ void load_ap(u64 ap[2][3][5], const float* At, int rr, int w0){
    #pragma unroll
    for (int ccv = 0; ccv < 2; ccv++){
        #pragma unroll
        for (int ky = 0; ky < 3; ky++){
            const float* arow = At + ccv*(6*AT_RS) + (rr + ky)*AT_RS + w0;
            float a0=arow[0], a1=arow[1], a2=arow[2], a3=arow[3], a4=arow[4], a5=arow[5];
            PACK2(ap[ccv][ky][0], a0, a1);
            PACK2(ap[ccv][ky][1], a1, a2);
            PACK2(ap[ccv][ky][2], a2, a3);
            PACK2(ap[ccv][ky][3], a3, a4);
            PACK2(ap[ccv][ky][4], a4, a5);
        }
    }
}

__device__ __forceinline__ void y_quad2(const u64 ap[2][3][5], const float* Us2, int o,
                                        float& o0, float& o1, float& o2, float& o3){
    u64 a01 = 0ull, a23 = 0ull;
    #pragma unroll
    for (int ccv = 0; ccv < 2; ccv++){
        const u64* up = (const u64*)Us2 + (ccv*64 + o)*9;
        #pragma unroll
        for (int ky = 0; ky < 3; ky++){
            u64 u0 = up[ky*3+0], u1 = up[ky*3+1], u2 = up[ky*3+2];
            FMA2(a01, u0, ap[ccv][ky][0]);
            FMA2(a01, u1, ap[ccv][ky][1]);
            FMA2(a01, u2, ap[ccv][ky][2]);
            FMA2(a23, u0, ap[ccv][ky][2]);
            FMA2(a23, u1, ap[ccv][ky][3]);
            FMA2(a23, u2, ap[ccv][ky][4]);
        }
    }
    UNPK(o0, o1, a01);
    UNPK(o2, o3, a23);
}

// ---------------- kernel 6: BN stats only ----------------
__global__ void y_kernel(){
    __shared__ float At[2*6*AT_RS];
    __shared__ float Us2[2304];
    __shared__ float bs[64], bsq[64];
    int b  = blockIdx.y;
    int h0 = blockIdx.x * YROWS;
    int t  = threadIdx.x;           // 192
    if (t < 64){ bs[t] = 0.f; bsq[t] = 0.f; }
    stage_AU2(At, Us2, b, h0, t);
    __syncthreads();

    int rr = t / 48, wq = t - rr*48;
    int w0 = wq * 4;
    u64 ap[2][3][5];
    load_ap(ap, At, rr, w0);
    for (int o = 0; o < 64; o++){
        float o0,o1,o2,o3;
        y_quad2(ap, Us2, o, o0, o1, o2, o3);
        float s1 = o0+o1+o2+o3;
        float s2 = o0*o0+o1*o1+o2*o2+o3*o3;
        #pragma unroll
        for (int off = 16; off > 0; off >>= 1){
            s1 += __shfl_down_sync(0xffffffffu, s1, off);
            s2 += __shfl_down_sync(0xffffffffu, s2, off);
        }
        if ((t & 31) == 0){ atomicAdd(&bs[o], s1); atomicAdd(&bsq[o], s2); }
    }
    __syncthreads();
    if (t < 64){ atomicAdd(&g_bnsum[t], bs[t]); atomicAdd(&g_bnsumsq[t], bsq[t]); }
}

// ---------------- kernel 7: BN finalize ----------------
__global__ void bnfin_kernel(const float* __restrict__ gamma, const float* __restrict__ beta){
    int o = threadIdx.x;
    float n = (float)(BB*HWW);
    float mean = g_bnsum[o] / n;
    float var  = g_bnsumsq[o] / n - mean*mean;
    float sc = gamma[o] * rsqrtf(var + 1e-5f);
    g_bnscale[o] = sc;
    g_bnbias[o]  = beta[o] - mean*sc;
}

// ---------------- kernel 8: recompute y, BN+ReLU, add x ----------------
__global__ void out_kernel(const float* __restrict__ x, float* __restrict__ out){
    __shared__ float At[2*6*AT_RS];
    __shared__ float Us2[2304];
    __shared__ float scs[64], bis[64];
    int b  = blockIdx.y;
    int h0 = blockIdx.x * YROWS;
    int t  = threadIdx.x;           // 192
    if (t < 64){ scs[t] = g_bnscale[t]; bis[t] = g_bnbias[t]; }
    stage_AU2(At, Us2, b, h0, t);
    __syncthreads();

    int rr = t / 48, wq = t - rr*48;
    int w0 = wq * 4;
    u64 ap[2][3][5];
    load_ap(ap, At, rr, w0);
    size_t rowoff = ((size_t)(b*64))*HWW + (size_t)(h0 + rr)*WWD + w0;
    for (int o = 0; o < 64; o++){
        float o0,o1,o2,o3;
        y_quad2(ap, Us2, o, o0, o1, o2, o3);
        float sc = scs[o], bi = bis[o];
        float4 xv = *(const float4*)&x[rowoff + (size_t)o*HWW];
        float4 r;
        r.x = xv.x + fmaxf(o0*sc + bi, 0.f);
        r.y = xv.y + fmaxf(o1*sc + bi, 0.f);
        r.z = xv.z + fmaxf(o2*sc + bi, 0.f);
        r.w = xv.w + fmaxf(o3*sc + bi, 0.f);
        *(float4*)&out[rowoff + (size_t)o*HWW] = r;
    }
}

// ---------------- launcher ----------------
extern "C" void kernel_launch(void* const* d_in, const int* in_sizes, int n_in,
                              void* d_out, int out_size){
    const float* x      = (const float*)d_in[0];
    const float* cs     = (const float*)d_in[1];
    const float* Wc     = (const float*)d_in[2];   // (7,1,3,3)
    const float* Wx     = (const float*)d_in[3];   // (512,64,3,3)
    const float* Wcs    = (const float*)d_in[4];   // (8,)
    const float* Wcv    = (const float*)d_in[5];   // (8,)
    const float* Wattn  = (const float*)d_in[6];   // (8,)
    const float* Wcomb  = (const float*)d_in[7];   // (8,)
    const float* Wsing  = (const float*)d_in[8];   // (64,64,3,3)
    const float* gamma  = (const float*)d_in[9];
    const float* beta   = (const float*)d_in[10];
    float* out = (float*)d_out;

    init_kernel<<<290, 256>>>();
    space_kernel<<<dim3(HH, BB*NCLS), 192>>>(cs, Wc);

    int corr_smem = (16*582 + 192*XS_STRIDE) * 4;   // 87936 bytes
    cudaFuncSetAttribute(corr_kernel, cudaFuncAttributeMaxDynamicSharedMemorySize, corr_smem);
    corr_kernel<<<dim3(HH/CH_ROWS, BB), 256, corr_smem>>>(x);

    tok2_kernel<<<512, 256>>>(Wx, Wcs);
    attn_kernel<<<dim3(HWW/256, BB*NCLS), 256>>>(cs, Wcv, Wattn, Wcomb);
    u_kernel<<<16, 576>>>(Wsing);
    y_kernel<<<dim3(HH/YROWS, BB), 192>>>();
    bnfin_kernel<<<1, 64>>>(gamma, beta);
    out_kernel<<<dim3(HH/YROWS, BB), 192>>>(x, out);
}

// round 6
// speedup vs baseline: 2.5309x; 1.4641x over previous
#include <cuda_runtime.h>
#include <math.h>

#define BB   8
#define CCH  64
#define HH   192
#define WWD  192
#define HWW  (HH*WWD)
#define NCLS 2
#define NSP  8

typedef unsigned long long u64;

// packed f32x2 helpers (Blackwell; FFMA2 only reachable via PTX)
#define FMA2(acc, a, b)   asm("fma.rn.f32x2 %0, %1, %2, %0;" : "+l"(acc) : "l"(a), "l"(b))
#define PACKD(d, f)       asm("mov.b64 %0, {%1, %1};" : "=l"(d) : "f"(f))
#define PACK2(d, lo, hi)  asm("mov.b64 %0, {%1, %2};" : "=l"(d) : "f"(lo), "f"(hi))
#define UNPK(lo, hi, d)   asm("mov.b64 {%0, %1}, %2;" : "=f"(lo), "=f"(hi) : "l"(d))

// ---------------- scratch (device globals; no allocation) ----------------
__device__ float g_space[BB*NCLS*NSP*HWW];   // [b][c][s][hw]  (tf32-rounded)
__device__ float g_A[BB*NCLS*HWW];           // [b][c][hw]
__device__ float g_R[BB*16*9*64];            // [b][sc][delta][e]
__device__ float g_S[BB*NCLS*NSP];           // per-map sums
__device__ float g_tok2[BB*NCLS*CCH];        // [b][c][d]
__device__ float g_U[BB*NCLS*CCH*9];         // [b][c][o][delta]
__device__ float g_bnsum[CCH];
__device__ float g_bnsumsq[CCH];
__device__ float g_bnscale[CCH];
__device__ float g_bnbias[CCH];

__device__ __forceinline__ float sigmoidf_(float x){ return 1.f/(1.f+__expf(-x)); }

__device__ __forceinline__ float tf32r(float f){
    unsigned u; asm("cvt.rna.tf32.f32 %0, %1;" : "=r"(u) : "f"(f));
    return __uint_as_float(u);
}

// ---------------- kernel 0: zero accumulators ----------------
__global__ void init_kernel(){
    int i = blockIdx.x*256 + threadIdx.x;
    if (i < BB*16*9*64) g_R[i] = 0.f;
    if (i < BB*NCLS*NSP) g_S[i] = 0.f;
    if (i < BB*NCLS*CCH) g_tok2[i] = 0.f;
    if (i < CCH){ g_bnsum[i] = 0.f; g_bnsumsq[i] = 0.f; }
}

// ---------------- kernel 1: space maps (tf32-rounded) + per-map sums ----------------
__global__ void space_kernel(const float* __restrict__ cs, const float* __restrict__ Wc){
    int h  = blockIdx.x;      // 0..191
    int bc = blockIdx.y;      // 0..15
    __shared__ float cp3[3*194];
    __shared__ float ssum[NSP];
    int t = threadIdx.x;      // 192
    if (t < NSP) ssum[t] = 0.f;
    const float* csp = cs + (size_t)bc*HWW;
    for (int idx = t; idx < 3*194; idx += 192){
        int r  = idx / 194;
        int wi = idx - r*194;
        int hh = h - 1 + r, ww = wi - 1;
        float v = 0.f;
        if (hh >= 0 && hh < HH && ww >= 0 && ww < WWD) v = sigmoidf_(csp[hh*WWD + ww]);
        cp3[idx] = v;
    }
    __syncthreads();
    int w = t;
    float sv[8];
    sv[0] = tf32r(cp3[194 + w + 1]);
    #pragma unroll
    for (int os = 0; os < 7; os++){
        float acc = 0.f;
        #pragma unroll
        for (int r = 0; r < 3; r++)
            #pragma unroll
            for (int c = 0; c < 3; c++)
                acc += Wc[os*9 + r*3 + c] * cp3[r*194 + w + c];
        sv[os+1] = tf32r(sigmoidf_(acc));
    }
    float* sp = g_space + ((size_t)bc*NSP)*HWW + h*WWD + w;
    #pragma unroll
    for (int s = 0; s < 8; s++){
        sp[(size_t)s*HWW] = sv[s];
        float v = sv[s];
        #pragma unroll
        for (int off = 16; off > 0; off >>= 1) v += __shfl_down_sync(0xffffffffu, v, off);
        if ((t & 31) == 0) atomicAdd(&ssum[s], v);
    }
    __syncthreads();
    if (t < NSP) atomicAdd(&g_S[bc*NSP + t], ssum[t]);
}

// ---------------- kernel 2: correlation GEMM on tensor cores (tf32) ----------------
// Per b: C[e=64][n=144] = sum_hw x[e,hw] * space[sc, hw - delta(di)],  n = sc*9+di
// mma.sync m16n8k8: 4 m-tiles (e) x 18 n-tiles; 8 warps = 4 mt x 2 n-groups of 9.
#define RW 6
__global__ void corr_tc_kernel(const float* __restrict__ x){
    extern __shared__ float sm[];
    float* ss = sm;            // 16 maps * 3 rows * 194 cols = 9312
    float* xs = sm + 9312;     // 64 e * 196 cols = 12544
    int b  = blockIdx.y;
    int h0 = blockIdx.x * RW;
    int t  = threadIdx.x;      // 256
    int warp = t >> 5, lane = t & 31;
    int lk = lane & 3, le = lane >> 2;
    int mt = warp & 3, ng = warp >> 2;
    int eb = mt*16 + le;

    // smem base offsets for B fragments: n = (ng*9+nt)*8 + le
    int bbase[9];
    #pragma unroll
    for (int nt = 0; nt < 9; nt++){
        int n = (ng*9 + nt)*8 + le;
        int sc = n / 9, di = n - sc*9;
        int ky = di/3, kx = di - ky*3;
        bbase[nt] = (sc*3 + (2-ky))*194 + (2-kx) + lk;
    }
    float acc[9][4];
    #pragma unroll
    for (int nt = 0; nt < 9; nt++){ acc[nt][0]=0.f; acc[nt][1]=0.f; acc[nt][2]=0.f; acc[nt][3]=0.f; }

    for (int rr = 0; rr < RW; rr++){
        int h = h0 + rr;
        __syncthreads();
        // stage space rows h-1..h+1, 16 maps, cols padded +-1 (already tf32-rounded)
        for (int idx = t; idx < 16*582; idx += 256){
            int sc  = idx / 582;
            int rem = idx - sc*582;
            int r   = rem / 194;
            int wi  = rem - r*194;
            int hh = h - 1 + r, ww = wi - 1;
            float v = 0.f;
            if (hh >= 0 && hh < HH && ww >= 0 && ww < WWD)
                v = g_space[((size_t)(b*16 + sc))*HWW + hh*WWD + ww];
            ss[idx] = v;
        }
        // stage x row h as xs[e][w], tf32-rounded, vectorized
        for (int idx = t; idx < 64*48; idx += 256){
            int e = idx / 48, wq = idx - e*48;
            float4 v = *(const float4*)&x[((size_t)(b*64+e))*HWW + h*WWD + wq*4];
            float4 r4;
            r4.x = tf32r(v.x); r4.y = tf32r(v.y); r4.z = tf32r(v.z); r4.w = tf32r(v.w);
            *(float4*)&xs[e*196 + wq*4] = r4;
        }
        __syncthreads();

        #pragma unroll 4
        for (int ks = 0; ks < 24; ks++){
            int k0 = ks*8;
            unsigned a0 = __float_as_uint(xs[eb*196     + k0 + lk]);
            unsigned a1 = __float_as_uint(xs[(eb+8)*196 + k0 + lk]);
            unsigned a2 = __float_as_uint(xs[eb*196     + k0 + lk + 4]);
            unsigned a3 = __float_as_uint(xs[(eb+8)*196 + k0 + lk + 4]);
            #pragma unroll
            for (int nt = 0; nt < 9; nt++){
                unsigned b0 = __float_as_uint(ss[bbase[nt] + k0]);
                unsigned b1 = __float_as_uint(ss[bbase[nt] + k0 + 4]);
                asm("mma.sync.aligned.m16n8k8.row.col.f32.tf32.tf32.f32 "
                    "{%0,%1,%2,%3}, {%4,%5,%6,%7}, {%8,%9}, {%0,%1,%2,%3};"
                    : "+f"(acc[nt][0]), "+f"(acc[nt][1]), "+f"(acc[nt][2]), "+f"(acc[nt][3])
                    : "r"(a0), "r"(a1), "r"(a2), "r"(a3), "r"(b0), "r"(b1));
            }
        }
    }
    // epilogue: C frag (e0/e0+8, n0/n0+1) -> g_R[b][sc][di][e]
    int e0 = mt*16 + le;
    #pragma unroll
    for (int nt = 0; nt < 9; nt++){
        int n0 = (ng*9 + nt)*8 + lk*2;
        int sc0 = n0 / 9,     di0 = n0 - sc0*9;
        int sc1 = (n0+1) / 9, di1 = (n0+1) - sc1*9;
        atomicAdd(&g_R[((size_t)(b*16 + sc0)*9 + di0)*64 + e0],     acc[nt][0]);
        atomicAdd(&g_R[((size_t)(b*16 + sc1)*9 + di1)*64 + e0],     acc[nt][1]);
        atomicAdd(&g_R[((size_t)(b*16 + sc0)*9 + di0)*64 + e0 + 8], acc[nt][2]);
        atomicAdd(&g_R[((size_t)(b*16 + sc1)*9 + di1)*64 + e0 + 8], acc[nt][3]);
    }
}

// ---------------- kernel 3: tok2 ----------------
__global__ void tok2_kernel(const float* __restrict__ Wx, const float* __restrict__ Wcs){
    __shared__ float wxs[576];          // reordered to [di*64+e]
    __shared__ float Rs[16*576];        // [bc][di*64+e]
    int s = blockIdx.x >> 6;
    int d = blockIdx.x & 63;
    int t = threadIdx.x;                // 256
    const float* wx = Wx + ((size_t)(s*64 + d))*576;
    for (int idx = t; idx < 576; idx += 256){
        int di = idx >> 6, e = idx & 63;
        wxs[idx] = wx[e*9 + di];
    }
    for (int idx = t; idx < 16*576; idx += 256){
        int bc = idx / 576, k = idx - bc*576;
        int b = bc >> 1, c = bc & 1;
        Rs[idx] = g_R[((size_t)(b*16 + c*8 + s))*576 + k];
    }
    __syncthreads();
    int bc = t >> 4, q = t & 15;
    const float* rr = Rs + bc*576;
    float p = 0.f;
    #pragma unroll 9
    for (int jj = 0; jj < 36; jj++){
        int k = q*36 + jj;
        p += wxs[k]*rr[k];
    }
    #pragma unroll
    for (int off = 8; off > 0; off >>= 1) p += __shfl_down_sync(0xffffffffu, p, off, 16);
    if (q == 0){
        float ws = Wcs[s] / g_S[bc*8 + s];
        atomicAdd(&g_tok2[bc*64 + d], ws*p);
    }
}

// ---------------- kernel 4: attention maps A ----------------
__global__ void attn_kernel(const float* __restrict__ cs, const float* __restrict__ Wcv,
                            const float* __restrict__ Wattn, const float* __restrict__ Wcomb){
    int bc = blockIdx.y;
    int hw = blockIdx.x*256 + threadIdx.x;
    float cp = sigmoidf_(cs[(size_t)bc*HWW + hw]);
    float a = 0.f;
    #pragma unroll
    for (int s = 0; s < 8; s++) a += Wcomb[s]*Wcv[s]*sigmoidf_(cp*Wattn[s]);
    g_A[(size_t)bc*HWW + hw] = a;
}

// ---------------- kernel 5: U[b,c,o,di] ----------------
__global__ void u_kernel(const float* __restrict__ Wsingle){
    int bc = blockIdx.x;
    int t  = threadIdx.x;           // 576
    __shared__ float tk[64];
    if (t < 64) tk[t] = g_tok2[bc*64 + t];
    __syncthreads();
    int o = t / 9, di = t - o*9;
    float acc = 0.f;
    for (int d = 0; d < 64; d++) acc += Wsingle[((size_t)(o*64 + d))*9 + di] * tk[d];
    g_U[(size_t)bc*576 + t] = acc;
}

// ---------------- shared y-compute helpers ----------------
#define YROWS 4
#define AT_RS 196
__device__ __forceinline__ void stage_AU2(float* At, float* Us2, int b, int h0, int t){
    for (int idx = t; idx < 2*6*194; idx += 192){
        int ccv = idx / (6*194);
        int rem = idx - ccv*(6*194);
        int r   = rem / 194;
        int wi  = rem - r*194;
        int hh = h0 - 1 + r, ww = wi - 1;
        float v = 0.f;
        if (hh >= 0 && hh < HH && ww >= 0 && ww < WWD)
            v = g_A[((size_t)(b*2 + ccv))*HWW + hh*WWD + ww];
        At[ccv*(6*AT_RS) + r*AT_RS + wi] = v;
    }
    for (int idx = t; idx < 1152; idx += 192){
        float v = g_U[(size_t)b*1152 + idx];
        Us2[2*idx]   = v;
        Us2[2*idx+1] = v;
    }
}

__device__ __forceinline__ void load_ap(u64 ap[2][3][5], const float* At, int rr, int w0){
    #pragma unroll
    for (int ccv = 0; ccv < 2; ccv++){
        #pragma unroll
        for (int ky = 0; ky < 3; ky++){
            const float* arow = At + ccv*(6*AT_RS) + (rr + ky)*AT_RS + w0;
            float a0=arow[0], a1=arow[1], a2=arow[2], a3=arow[3], a4=arow[4], a5=arow[5];
            PACK2(ap[ccv][ky][0], a0, a1);
            PACK2(ap[ccv][ky][1], a1, a2);
            PACK2(ap[ccv][ky][2], a2, a3);
            PACK2(ap[ccv][ky][3], a3, a4);
            PACK2(ap[ccv][ky][4], a4, a5);
        }
    }
}

__device__ __forceinline__ void y_quad2(const u64 ap[2][3][5], const float* Us2, int o,
                                        float& o0, float& o1, float& o2, float& o3){
    u64 a01 = 0ull, a23 = 0ull;
    #pragma unroll
    for (int ccv = 0; ccv < 2; ccv++){
        const u64* up = (const u64*)Us2 + (ccv*64 + o)*9;
        #pragma unroll
        for (int ky = 0; ky < 3; ky++){
            u64 u0 = up[ky*3+0], u1 = up[ky*3+1], u2 = up[ky*3+2];
            FMA2(a01, u0, ap[ccv][ky][0]);
            FMA2(a01, u1, ap[ccv][ky][1]);
            FMA2(a01, u2, ap[ccv][ky][2]);
            FMA2(a23, u0, ap[ccv][ky][2]);
            FMA2(a23, u1, ap[ccv][ky][3]);
            FMA2(a23, u2, ap[ccv][ky][4]);
        }
    }
    UNPK(o0, o1, a01);
    UNPK(o2, o3, a23);
}

// ---------------- kernel 6: BN stats only ----------------
__global__ void y_kernel(){
    __shared__ float At[2*6*AT_RS];
    __shared__ float Us2[2304];
    __shared__ float bs[64], bsq[64];
    int b  = blockIdx.y;
    int h0 = blockIdx.x * YROWS;
    int t  = threadIdx.x;           // 192
    if (t < 64){ bs[t] = 0.f; bsq[t] = 0.f; }
    stage_AU2(At, Us2, b, h0, t);
    __syncthreads();

    int rr = t / 48, wq = t - rr*48;
    int w0 = wq * 4;
    u64 ap[2][3][5];
    load_ap(ap, At, rr, w0);
    for (int o = 0; o < 64; o++){
        float o0,o1,o2,o3;
        y_quad2(ap, Us2, o, o0, o1, o2, o3);
        float s1 = o0+o1+o2+o3;
        float s2 = o0*o0+o1*o1+o2*o2+o3*o3;
        #pragma unroll
        for (int off = 16; off > 0; off >>= 1){
            s1 += __shfl_down_sync(0xffffffffu, s1, off);
            s2 += __shfl_down_sync(0xffffffffu, s2, off);
        }
        if ((t & 31) == 0){ atomicAdd(&bs[o], s1); atomicAdd(&bsq[o], s2); }
    }
    __syncthreads();
    if (t < 64){ atomicAdd(&g_bnsum[t], bs[t]); atomicAdd(&g_bnsumsq[t], bsq[t]); }
}

// ---------------- kernel 7: BN finalize ----------------
__global__ void bnfin_kernel(const float* __restrict__ gamma, const float* __restrict__ beta){
    int o = threadIdx.x;
    float n = (float)(BB*HWW);
    float mean = g_bnsum[o] / n;
    float var  = g_bnsumsq[o] / n - mean*mean;
    float sc = gamma[o] * rsqrtf(var + 1e-5f);
    g_bnscale[o] = sc;
    g_bnbias[o]  = beta[o] - mean*sc;
}

// ---------------- kernel 8: recompute y, BN+ReLU, add x ----------------
__global__ void out_kernel(const float* __restrict__ x, float* __restrict__ out){
    __shared__ float At[2*6*AT_RS];
    __shared__ float Us2[2304];
    __shared__ float scs[64], bis[64];
    int b  = blockIdx.y;
    int h0 = blockIdx.x * YROWS;
    int t  = threadIdx.x;           // 192
    if (t < 64){ scs[t] = g_bnscale[t]; bis[t] = g_bnbias[t]; }
    stage_AU2(At, Us2, b, h0, t);
    __syncthreads();

    int rr = t / 48, wq = t - rr*48;
    int w0 = wq * 4;
    u64 ap[2][3][5];
    load_ap(ap, At, rr, w0);
    size_t rowoff = ((size_t)(b*64))*HWW + (size_t)(h0 + rr)*WWD + w0;
    for (int o = 0; o < 64; o++){
        float o0,o1,o2,o3;
        y_quad2(ap, Us2, o, o0, o1, o2, o3);
        float sc = scs[o], bi = bis[o];
        float4 xv = *(const float4*)&x[rowoff + (size_t)o*HWW];
        float4 r;
        r.x = xv.x + fmaxf(o0*sc + bi, 0.f);
        r.y = xv.y + fmaxf(o1*sc + bi, 0.f);
        r.z = xv.z + fmaxf(o2*sc + bi, 0.f);
        r.w = xv.w + fmaxf(o3*sc + bi, 0.f);
        *(float4*)&out[rowoff + (size_t)o*HWW] = r;
    }
}

// ---------------- launcher ----------------
extern "C" void kernel_launch(void* const* d_in, const int* in_sizes, int n_in,
                              void* d_out, int out_size){
    const float* x      = (const float*)d_in[0];
    const float* cs     = (const float*)d_in[1];
    const float* Wc     = (const float*)d_in[2];   // (7,1,3,3)
    const float* Wx     = (const float*)d_in[3];   // (512,64,3,3)
    const float* Wcs    = (const float*)d_in[4];   // (8,)
    const float* Wcv    = (const float*)d_in[5];   // (8,)
    const float* Wattn  = (const float*)d_in[6];   // (8,)
    const float* Wcomb  = (const float*)d_in[7];   // (8,)
    const float* Wsing  = (const float*)d_in[8];   // (64,64,3,3)
    const float* gamma  = (const float*)d_in[9];
    const float* beta   = (const float*)d_in[10];
    float* out = (float*)d_out;

    init_kernel<<<290, 256>>>();
    space_kernel<<<dim3(HH, BB*NCLS), 192>>>(cs, Wc);

    int corr_smem = (16*582 + 64*196) * 4;   // 87424 bytes
    cudaFuncSetAttribute(corr_tc_kernel, cudaFuncAttributeMaxDynamicSharedMemorySize, corr_smem);
    corr_tc_kernel<<<dim3(HH/RW, BB), 256, corr_smem>>>(x);

    tok2_kernel<<<512, 256>>>(Wx, Wcs);
    attn_kernel<<<dim3(HWW/256, BB*NCLS), 256>>>(cs, Wcv, Wattn, Wcomb);
    u_kernel<<<16, 576>>>(Wsing);
    y_kernel<<<dim3(HH/YROWS, BB), 192>>>();
    bnfin_kernel<<<1, 64>>>(gamma, beta);
    out_kernel<<<dim3(HH/YROWS, BB), 192>>>(x, out);
}